// round 6
// baseline (speedup 1.0000x reference)
#include <cuda_runtime.h>
#include <cuda_bf16.h>
#include <math_constants.h>

// ProbAttention (Informer ProbSparse) — B=4, L=S=2048, H=8, D=64, sample_k=n_top=40.
// Inputs (metadata order): queries f32 [B,L,H,D], keys f32 [B,S,H,D],
//                          values f32 [B,S,H,D], index_sample i32 [L,40].
// Output f32 [B,L,H,D].

#define B_ 4
#define L_ 2048
#define S_ 2048
#define H_ 8
#define D_ 64
#define SK_ 40
#define NTOP_ 40
#define BH_ (B_ * H_)
#define SCALE_ 0.125f
#define QPB_ 4                      // queries per attention block
#define QBLKS_ (NTOP_ / QPB_)       // 10 blocks per (b,h)

// Scratch (allocation-free rule: __device__ globals)
__device__ float g_M[BH_ * L_];
__device__ int   g_top[BH_ * NTOP_];
__device__ float g_vmean[BH_ * D_];

// ---------------------------------------------------------------------------
// K1: sampled QK -> M[bh, l] = max_u(q.k_u) - sum_u(q.k_u)/S
// One warp per (b,h,l). Lane holds dims {lane, lane+32} of q in registers.
// ---------------------------------------------------------------------------
__global__ void k_sample(const float* __restrict__ q,
                         const float* __restrict__ k,
                         const int* __restrict__ idxs) {
    int warp = (blockIdx.x * blockDim.x + threadIdx.x) >> 5;
    int lane = threadIdx.x & 31;
    if (warp >= BH_ * L_) return;
    int l  = warp & (L_ - 1);
    int bh = warp >> 11;
    int b = bh >> 3, h = bh & 7;

    const float* qrow = q + (((size_t)(b * L_ + l)) * H_ + h) * D_;
    float q0 = qrow[lane];
    float q1 = qrow[lane + 32];

    float mx = -CUDART_INF_F, sm = 0.f;
    const int* il = idxs + l * SK_;
    #pragma unroll 4
    for (int u = 0; u < SK_; u++) {
        int s = __ldg(il + u);
        const float* krow = k + (((size_t)(b * S_ + s)) * H_ + h) * D_;
        float p = q0 * krow[lane] + q1 * krow[lane + 32];
        p += __shfl_xor_sync(0xFFFFFFFFu, p, 16);
        p += __shfl_xor_sync(0xFFFFFFFFu, p, 8);
        p += __shfl_xor_sync(0xFFFFFFFFu, p, 4);
        p += __shfl_xor_sync(0xFFFFFFFFu, p, 2);
        p += __shfl_xor_sync(0xFFFFFFFFu, p, 1);
        mx = fmaxf(mx, p);
        sm += p;
    }
    if (lane == 0) g_M[warp] = mx - sm * (1.0f / (float)S_);
}

// ---------------------------------------------------------------------------
// K2: top-40 of M per (b,h). Iterative argmax, tie -> smaller index
// (matches jax.lax.top_k ordering semantics for the selected set).
// ---------------------------------------------------------------------------
__global__ void k_topk() {
    int bh = blockIdx.x;
    int tid = threadIdx.x;  // 256 threads
    __shared__ float sM[L_];
    __shared__ float rv[256];
    __shared__ int   ri[256];

    for (int i = tid; i < L_; i += 256) sM[i] = g_M[bh * L_ + i];
    __syncthreads();

    for (int t = 0; t < NTOP_; t++) {
        float bv = -CUDART_INF_F; int bi = 0x7FFFFFFF;
        for (int i = tid; i < L_; i += 256) {
            float v = sM[i];
            if (v > bv) { bv = v; bi = i; }
        }
        rv[tid] = bv; ri[tid] = bi;
        __syncthreads();
        for (int off = 128; off > 0; off >>= 1) {
            if (tid < off) {
                float ov = rv[tid + off]; int oi = ri[tid + off];
                if (ov > rv[tid] || (ov == rv[tid] && oi < ri[tid])) {
                    rv[tid] = ov; ri[tid] = oi;
                }
            }
            __syncthreads();
        }
        if (tid == 0) { g_top[bh * NTOP_ + t] = ri[0]; sM[ri[0]] = -CUDART_INF_F; }
        __syncthreads();
    }
}

// ---------------------------------------------------------------------------
// K3: vmean[bh, d] = mean_s v[b,s,h,d]
// ---------------------------------------------------------------------------
__global__ void k_vmean(const float* __restrict__ v) {
    int bh = blockIdx.x;
    int b = bh >> 3, h = bh & 7;
    int tid = threadIdx.x;       // 256
    int d = tid & 63, g = tid >> 6;
    float s = 0.f;
    for (int r = g; r < S_; r += 4)
        s += v[(((size_t)(b * S_ + r)) * H_ + h) * D_ + d];
    __shared__ float part[4][D_];
    part[g][d] = s;
    __syncthreads();
    if (g == 0)
        g_vmean[bh * D_ + d] =
            (part[0][d] + part[1][d] + part[2][d] + part[3][d]) * (1.0f / (float)S_);
}

// ---------------------------------------------------------------------------
// K4: out[b,l,h,d] = vmean[bh,d]  (float4 stores, full coverage)
// ---------------------------------------------------------------------------
__global__ void k_fill(float4* __restrict__ out) {
    // total float4s: B*L*H*16 = 1,048,576
    unsigned i = blockIdx.x * blockDim.x + threadIdx.x;
    if (i >= (unsigned)(B_ * L_ * H_ * (D_ / 4))) return;
    unsigned d4 = i & 15u;
    unsigned h  = (i >> 4) & 7u;
    unsigned b  = i >> 18;
    const float4* vm = (const float4*)g_vmean;
    out[i] = __ldg(vm + ((b * H_ + h) * (D_ / 4) + d4));
}

// ---------------------------------------------------------------------------
// K5: dense attention for selected queries. 4 queries/block, scores in smem.
// grid = BH_ * QBLKS_ = 320, block = 256.
// ---------------------------------------------------------------------------
__global__ __launch_bounds__(256) void k_attn(const float* __restrict__ q,
                                              const float* __restrict__ k,
                                              const float* __restrict__ v,
                                              float* __restrict__ out) {
    int bh = blockIdx.x / QBLKS_;
    int qb = blockIdx.x % QBLKS_;
    int b = bh >> 3, h = bh & 7;
    int tid = threadIdx.x;

    __shared__ float sq[QPB_][D_];
    __shared__ float sc[QPB_][S_];          // 32 KB
    __shared__ float sZ[QPB_];
    __shared__ int   sl[QPB_];
    __shared__ float pr[4][QPB_][D_];

    // Load selected queries (pre-scaled)
    if (tid < QPB_ * D_) {
        int qi = tid >> 6, d = tid & 63;
        int lsel = g_top[bh * NTOP_ + qb * QPB_ + qi];
        if (d == 0) sl[qi] = lsel;
        sq[qi][d] = q[(((size_t)(b * L_ + lsel)) * H_ + h) * D_ + d] * SCALE_;
    }
    __syncthreads();

    // Scores: each thread streams k-rows s = tid, tid+256, ...
    for (int s = tid; s < S_; s += 256) {
        const float4* krow = (const float4*)(k + (((size_t)(b * S_ + s)) * H_ + h) * D_);
        float4 kr[16];
        #pragma unroll
        for (int j = 0; j < 16; j++) kr[j] = krow[j];
        #pragma unroll
        for (int qi = 0; qi < QPB_; qi++) {
            const float4* qq4 = (const float4*)sq[qi];
            float acc = 0.f;
            #pragma unroll
            for (int j = 0; j < 16; j++) {
                float4 qq = qq4[j];
                acc += qq.x * kr[j].x + qq.y * kr[j].y + qq.z * kr[j].z + qq.w * kr[j].w;
            }
            sc[qi][s] = acc;
        }
    }
    __syncthreads();

    // Softmax: warp qi handles query qi (warps 0..3)
    int w = tid >> 5, lane = tid & 31;
    if (w < QPB_) {
        float mx = -CUDART_INF_F;
        for (int s = lane; s < S_; s += 32) mx = fmaxf(mx, sc[w][s]);
        #pragma unroll
        for (int o = 16; o; o >>= 1) mx = fmaxf(mx, __shfl_xor_sync(0xFFFFFFFFu, mx, o));
        float sum = 0.f;
        for (int s = lane; s < S_; s += 32) {
            float e = __expf(sc[w][s] - mx);
            sc[w][s] = e;
            sum += e;
        }
        #pragma unroll
        for (int o = 16; o; o >>= 1) sum += __shfl_xor_sync(0xFFFFFFFFu, sum, o);
        if (lane == 0) sZ[w] = sum;
    }
    __syncthreads();

    // AV: thread = (d, g); g strides over s; coalesced v reads across d.
    int d = tid & 63, g = tid >> 6;
    float acc[QPB_] = {0.f, 0.f, 0.f, 0.f};
    for (int s = g; s < S_; s += 4) {
        float vv = v[(((size_t)(b * S_ + s)) * H_ + h) * D_ + d];
        #pragma unroll
        for (int qi = 0; qi < QPB_; qi++) acc[qi] += sc[qi][s] * vv;
    }
    #pragma unroll
    for (int qi = 0; qi < QPB_; qi++) pr[g][qi][d] = acc[qi];
    __syncthreads();
    if (g < QPB_) {
        int qi = g;
        float r = (pr[0][qi][d] + pr[1][qi][d] + pr[2][qi][d] + pr[3][qi][d]) / sZ[qi];
        out[(((size_t)(b * L_ + sl[qi])) * H_ + h) * D_ + d] = r;
    }
}

// ---------------------------------------------------------------------------
extern "C" void kernel_launch(void* const* d_in, const int* in_sizes, int n_in,
                              void* d_out, int out_size) {
    const float* q   = (const float*)d_in[0];
    const float* k   = (const float*)d_in[1];
    const float* v   = (const float*)d_in[2];
    const int*   idx = (const int*)d_in[3];
    float* out = (float*)d_out;

    // K1: one warp per (b,h,l): 65536 warps, 8 warps/block
    k_sample<<<(BH_ * L_) / 8, 256>>>(q, k, idx);
    // K2: top-40 per (b,h)
    k_topk<<<BH_, 256>>>();
    // K3: v mean
    k_vmean<<<BH_, 256>>>(v);
    // K4: broadcast fill of output
    {
        unsigned n4 = B_ * L_ * H_ * (D_ / 4);
        k_fill<<<(n4 + 255) / 256, 256>>>((float4*)out);
    }
    // K5: dense attention for selected rows (overwrites filled rows)
    k_attn<<<BH_ * QBLKS_, 256>>>(q, k, v, out);
}